// round 1
// baseline (speedup 1.0000x reference)
#include <cuda_runtime.h>
#include <cuda_bf16.h>

// Problem constants (from reference: B=256, D=512)
#define B_ROWS 256
#define D_COLS 512

// Scratch for per-column partial results (no device allocation allowed).
__device__ double g_col_partial[D_COLS];

// Kernel A: one block per column d, one thread per row i.
// Computes the 6 per-column sums and the column's contribution:
//   c_d = S_var*S_inv + S_mu2*S_inv - 2*S_mu*S_muinv + B*S_mu2inv - B^2
__global__ __launch_bounds__(B_ROWS) void kl_col_kernel(
    const float* __restrict__ mu, const float* __restrict__ logvar)
{
    const int d = blockIdx.x;
    const int i = threadIdx.x;

    const float m  = mu[i * D_COLS + d];
    const float l  = logvar[i * D_COLS + d];
    const float v  = __expf(l);    // var
    const float iv = __expf(-l);   // 1/var

    float s0 = v;          // sum var
    float s1 = iv;         // sum inv-var
    float s2 = m;          // sum mu
    float s3 = m * m;      // sum mu^2
    float s4 = m * iv;     // sum mu*inv
    float s5 = m * m * iv; // sum mu^2*inv

    // Warp-level tree reduce of all 6 sums
    #pragma unroll
    for (int off = 16; off > 0; off >>= 1) {
        s0 += __shfl_down_sync(0xFFFFFFFFu, s0, off);
        s1 += __shfl_down_sync(0xFFFFFFFFu, s1, off);
        s2 += __shfl_down_sync(0xFFFFFFFFu, s2, off);
        s3 += __shfl_down_sync(0xFFFFFFFFu, s3, off);
        s4 += __shfl_down_sync(0xFFFFFFFFu, s4, off);
        s5 += __shfl_down_sync(0xFFFFFFFFu, s5, off);
    }

    __shared__ float sh[6][8];  // 8 warps
    const int warp = i >> 5;
    const int lane = i & 31;
    if (lane == 0) {
        sh[0][warp] = s0; sh[1][warp] = s1; sh[2][warp] = s2;
        sh[3][warp] = s3; sh[4][warp] = s4; sh[5][warp] = s5;
    }
    __syncthreads();

    if (i == 0) {
        float t0 = 0.f, t1 = 0.f, t2 = 0.f, t3 = 0.f, t4 = 0.f, t5 = 0.f;
        #pragma unroll
        for (int w = 0; w < 8; w++) {
            t0 += sh[0][w]; t1 += sh[1][w]; t2 += sh[2][w];
            t3 += sh[3][w]; t4 += sh[4][w]; t5 += sh[5][w];
        }
        const double Bf = (double)B_ROWS;
        double c = (double)t0 * (double)t1          // S_var * S_inv
                 + (double)t3 * (double)t1          // S_mu2 * S_inv
                 - 2.0 * (double)t2 * (double)t4    // -2 * S_mu * S_muinv
                 + Bf * (double)t5                  // B * S_mu2inv
                 - Bf * Bf;                         // - B^2 (the "-1" term)
        g_col_partial[d] = c;
    }
}

// Kernel B: deterministic reduce of 512 doubles -> scaled scalar float.
__global__ __launch_bounds__(D_COLS) void kl_reduce_kernel(float* __restrict__ out)
{
    const int t = threadIdx.x;
    double x = g_col_partial[t];

    // Warp reduce (doubles work with shfl on sm_103a)
    #pragma unroll
    for (int off = 16; off > 0; off >>= 1)
        x += __shfl_down_sync(0xFFFFFFFFu, x, off);

    __shared__ double sh[16];  // 512/32 warps
    const int warp = t >> 5;
    const int lane = t & 31;
    if (lane == 0) sh[warp] = x;
    __syncthreads();

    if (t == 0) {
        double total = 0.0;
        #pragma unroll
        for (int w = 0; w < 16; w++) total += sh[w];
        out[0] = (float)(total * (0.5 / (double)B_ROWS));
    }
}

extern "C" void kernel_launch(void* const* d_in, const int* in_sizes, int n_in,
                              void* d_out, int out_size)
{
    const float* mu = (const float*)d_in[0];
    const float* lv = (const float*)d_in[1];
    float* out = (float*)d_out;

    kl_col_kernel<<<D_COLS, B_ROWS>>>(mu, lv);
    kl_reduce_kernel<<<1, D_COLS>>>(out);
}

// round 2
// speedup vs baseline: 1.4781x; 1.4781x over previous
#include <cuda_runtime.h>
#include <cuda_bf16.h>

// Problem constants (B=256 rows, D=512 cols, row-major [B, D])
#define B_ROWS 256
#define D_COLS 512
#define CPB 8               // columns per block
#define GRID (D_COLS / CPB) // 64 blocks
#define THREADS 256
#define RPT (B_ROWS / (THREADS / CPB)) // 8 rows per thread

// Scratch (no device allocation allowed)
__device__ float g_col_partial[D_COLS];
__device__ int   g_counter = 0;

__global__ __launch_bounds__(THREADS) void kl_fused_kernel(
    const float* __restrict__ mu, const float* __restrict__ logvar,
    float* __restrict__ out)
{
    const int tid = threadIdx.x;
    const int c    = tid & (CPB - 1);      // column within this block's group
    const int rb   = tid >> 3;             // 0..31 row base
    const int d    = blockIdx.x * CPB + c; // global column

    // ---- Phase 1: per-thread partial sums over 8 rows ----
    float s0 = 0.f, s1 = 0.f, s2 = 0.f, s3 = 0.f, s4 = 0.f, s5 = 0.f;
    #pragma unroll
    for (int k = 0; k < RPT; k++) {
        const int i = rb + k * 32;
        const float m  = mu[i * D_COLS + d];
        const float l  = logvar[i * D_COLS + d];
        const float v  = __expf(l);
        const float iv = __expf(-l);
        s0 += v;          // sum var
        s1 += iv;         // sum 1/var
        s2 += m;          // sum mu
        s3 += m * m;      // sum mu^2
        s4 += m * iv;     // sum mu/var
        s5 += m * m * iv; // sum mu^2/var
    }

    // ---- Warp reduce: lanes {c, c+8, c+16, c+24} share a column ----
    #pragma unroll
    for (int off = 16; off >= 8; off >>= 1) {
        s0 += __shfl_down_sync(0xFFFFFFFFu, s0, off);
        s1 += __shfl_down_sync(0xFFFFFFFFu, s1, off);
        s2 += __shfl_down_sync(0xFFFFFFFFu, s2, off);
        s3 += __shfl_down_sync(0xFFFFFFFFu, s3, off);
        s4 += __shfl_down_sync(0xFFFFFFFFu, s4, off);
        s5 += __shfl_down_sync(0xFFFFFFFFu, s5, off);
    }

    __shared__ float sh[6][8][CPB];   // [stat][warp][col]
    const int warp = tid >> 5;
    const int lane = tid & 31;
    if (lane < CPB) {
        sh[0][warp][lane] = s0; sh[1][warp][lane] = s1; sh[2][warp][lane] = s2;
        sh[3][warp][lane] = s3; sh[4][warp][lane] = s4; sh[5][warp][lane] = s5;
    }
    __syncthreads();

    // ---- Combine across 8 warps; threads 0..7 own one column each ----
    if (tid < CPB) {
        float t0 = 0.f, t1 = 0.f, t2 = 0.f, t3 = 0.f, t4 = 0.f, t5 = 0.f;
        #pragma unroll
        for (int w = 0; w < 8; w++) {
            t0 += sh[0][w][tid]; t1 += sh[1][w][tid]; t2 += sh[2][w][tid];
            t3 += sh[3][w][tid]; t4 += sh[4][w][tid]; t5 += sh[5][w][tid];
        }
        const float Bf = (float)B_ROWS;
        // c_d = S_var*S_inv + S_mu2*S_inv - 2*S_mu*S_muinv + B*S_mu2inv - B^2
        float cd = t0 * t1 + t3 * t1 - 2.0f * t2 * t4 + Bf * t5 - Bf * Bf;
        g_col_partial[blockIdx.x * CPB + tid] = cd;
    }

    // ---- Last-block final reduce (threadfence-reduction pattern) ----
    __shared__ int is_last;
    __threadfence();
    __syncthreads();
    if (tid == 0) {
        int prev = atomicAdd(&g_counter, 1);
        is_last = (prev == GRID - 1);
    }
    __syncthreads();

    if (is_last) {
        // 512 partials, 256 threads: 2 each
        float x = g_col_partial[tid] + g_col_partial[tid + THREADS];
        #pragma unroll
        for (int off = 16; off > 0; off >>= 1)
            x += __shfl_down_sync(0xFFFFFFFFu, x, off);

        __shared__ float shr[8];
        if (lane == 0) shr[warp] = x;
        __syncthreads();
        if (tid == 0) {
            float total = 0.f;
            #pragma unroll
            for (int w = 0; w < 8; w++) total += shr[w];
            out[0] = total * (0.5f / (float)B_ROWS);
            g_counter = 0;  // reset for next graph replay
        }
    }
}

extern "C" void kernel_launch(void* const* d_in, const int* in_sizes, int n_in,
                              void* d_out, int out_size)
{
    const float* mu = (const float*)d_in[0];
    const float* lv = (const float*)d_in[1];
    float* out = (float*)d_out;

    kl_fused_kernel<<<GRID, THREADS>>>(mu, lv, out);
}